// round 9
// baseline (speedup 1.0000x reference)
#include <cuda_runtime.h>
#include <cuda_bf16.h>
#include <cstddef>
#include <cstdint>

#define N_AGENTS 8192
#define HIDDEN   256
#define MSG      128
#define KEY      64
#define NSPLIT   4
#define COLS_PER_SPLIT (N_AGENTS / NSPLIT)   // 2048
#define NT (COLS_PER_SPLIT / 128)            // 16 j-tiles per block

// ---------------- scratch (no allocations allowed) ----------------
__device__ float g_qkm[N_AGENTS * 256];
__device__ float g_S  [N_AGENTS];
__device__ float g_S_part[NSPLIT * N_AGENTS];
__device__ float g_att_part[NSPLIT * N_AGENTS * MSG];
__device__ float g_GA[N_AGENTS * 768];
__device__ float g_GB[N_AGENTS * 768];
__device__ float g_bias_p[256];
__device__ float g_bias_i[768];

__device__ __align__(16) __nv_bfloat16 g_kh[N_AGENTS * KEY];
__device__ __align__(16) __nv_bfloat16 g_kl[N_AGENTS * KEY];
__device__ __align__(16) __nv_bfloat16 g_qh[N_AGENTS * KEY];   // prescaled by 1/8
__device__ __align__(16) __nv_bfloat16 g_ql[N_AGENTS * KEY];
__device__ __align__(16) __nv_bfloat16 g_mTh[MSG * N_AGENTS];
__device__ __align__(16) __nv_bfloat16 g_mTl[MSG * N_AGENTS];
__device__ __align__(16) __nv_bfloat16 g_hh[N_AGENTS * HIDDEN];
__device__ __align__(16) __nv_bfloat16 g_hl[N_AGENTS * HIDDEN];
__device__ __align__(16) __nv_bfloat16 g_ath[N_AGENTS * MSG];
__device__ __align__(16) __nv_bfloat16 g_atl[N_AGENTS * MSG];
__device__ __align__(16) __nv_bfloat16 g_Wp_h[256 * 256];
__device__ __align__(16) __nv_bfloat16 g_Wp_l[256 * 256];
__device__ __align__(16) __nv_bfloat16 g_Wi_h[768 * 128];
__device__ __align__(16) __nv_bfloat16 g_Wi_l[768 * 128];
__device__ __align__(16) __nv_bfloat16 g_Wh_h[768 * 256];
__device__ __align__(16) __nv_bfloat16 g_Wh_l[768 * 256];

// ---------------- PTX helpers (compute_103-safe) ----------------
__device__ __forceinline__ uint32_t smem_u32(const void* p) {
    uint32_t a;
    asm("{ .reg .u64 t; cvta.to.shared.u64 t, %1; cvt.u32.u64 %0, t; }" : "=r"(a) : "l"(p));
    return a;
}

#define LDSM_X4(r0, r1, r2, r3, addr) \
    asm volatile("ldmatrix.sync.aligned.m8n8.x4.shared.b16 {%0,%1,%2,%3}, [%4];" \
                 : "=r"(r0), "=r"(r1), "=r"(r2), "=r"(r3) : "r"(addr))

#define MMA_BF16(C, A, B0, B1) \
    asm volatile("mma.sync.aligned.m16n8k16.row.col.f32.bf16.bf16.f32 " \
                 "{%0,%1,%2,%3}, {%4,%5,%6,%7}, {%8,%9}, {%0,%1,%2,%3};" \
                 : "+f"((C)[0]), "+f"((C)[1]), "+f"((C)[2]), "+f"((C)[3]) \
                 : "r"((A)[0]), "r"((A)[1]), "r"((A)[2]), "r"((A)[3]), \
                   "r"(B0), "r"(B1))

__device__ __forceinline__ uint32_t pack_bf(__nv_bfloat16 a, __nv_bfloat16 b) {
    return (uint32_t)__bfloat16_as_ushort(a) | ((uint32_t)__bfloat16_as_ushort(b) << 16);
}

// ---------------- attention smem (single stage; 2 blocks/SM) ----------------
#define KSTR 72
#define MSTR 136
#define S_KL (128 * KSTR)
#define S_MH (2 * 128 * KSTR)
#define S_ML (S_MH + 128 * MSTR)
#define STAGE_ELEMS (2 * 128 * KSTR + 2 * 128 * MSTR)   // 53248 bf16
#define ATTN_SMEM (STAGE_ELEMS * 2)                     // 106496 bytes

__global__ __launch_bounds__(256, 2) void attn_mma_kernel(float* __restrict__ E_out)
{
    extern __shared__ __nv_bfloat16 sm[];
    __nv_bfloat16* Kh = sm;
    __nv_bfloat16* Kl = sm + S_KL;
    __nv_bfloat16* Mh = sm + S_MH;
    __nv_bfloat16* Ml = sm + S_ML;

    const int tid  = threadIdx.x;
    const int w    = tid >> 5, lane = tid & 31;
    const int tr   = lane >> 2;
    const int tc   = lane & 3;
    const int row0 = w * 16;
    const int i0    = blockIdx.x * 128;
    const int jbase = blockIdx.y * COLS_PER_SPLIT;

    // ---- stage Q (hi/lo) into K buffers, extract persistent fragments ----
    #pragma unroll
    for (int it = 0; it < 4; it++) {
        int idx = tid + it * 256;
        int r = idx >> 3, ch = idx & 7;
        *(uint4*)&Kh[r * KSTR + ch * 8] =
            *(const uint4*)&g_qh[(size_t)(i0 + r) * KEY + ch * 8];
        *(uint4*)&Kl[r * KSTR + ch * 8] =
            *(const uint4*)&g_ql[(size_t)(i0 + r) * KEY + ch * 8];
    }
    __syncthreads();

    uint32_t qh[4][4], ql[4][4];
    {
        int octet = lane >> 3;
        int rr = row0 + (octet & 1) * 8 + (lane & 7);
        int kk = (octet >> 1) * 8;
        #pragma unroll
        for (int ks = 0; ks < 4; ks++) {
            LDSM_X4(qh[ks][0], qh[ks][1], qh[ks][2], qh[ks][3],
                    smem_u32(&Kh[rr * KSTR + ks * 16 + kk]));
            LDSM_X4(ql[ks][0], ql[ks][1], ql[ks][2], ql[ks][3],
                    smem_u32(&Kl[rr * KSTR + ks * 16 + kk]));
        }
    }

    float at[16][4];
    #pragma unroll
    for (int n = 0; n < 16; n++)
        #pragma unroll
        for (int q = 0; q < 4; q++) at[n][q] = 0.f;
    float rs0 = 0.f, rs1 = 0.f;

    const int gr0 = i0 + row0 + tr;
    const int gr1 = gr0 + 8;

    for (int t = 0; t < NT; t++) {
        const size_t j0 = (size_t)(jbase + t * 128);
        __syncthreads();   // previous tile consumed (and Q extraction done at t=0)
        #pragma unroll
        for (int it = 0; it < 4; it++) {
            int idx = tid + it * 256;
            int r = idx >> 3, ch = idx & 7;
            *(uint4*)&Kh[r * KSTR + ch * 8] = *(const uint4*)&g_kh[(j0 + r) * KEY + ch * 8];
            *(uint4*)&Kl[r * KSTR + ch * 8] = *(const uint4*)&g_kl[(j0 + r) * KEY + ch * 8];
        }
        #pragma unroll
        for (int it = 0; it < 8; it++) {
            int idx = tid + it * 256;
            int c = idx >> 4, ch = idx & 15;
            *(uint4*)&Mh[c * MSTR + ch * 8] = *(const uint4*)&g_mTh[(size_t)c * N_AGENTS + j0 + ch * 8];
            *(uint4*)&Ml[c * MSTR + ch * 8] = *(const uint4*)&g_mTl[(size_t)c * N_AGENTS + j0 + ch * 8];
        }
        __syncthreads();

        // process in two n-halves to keep cs register footprint at 8x4
        #pragma unroll
        for (int hf = 0; hf < 2; hf++) {
            float cs[8][4];
            // ---- scores for n-tiles hf*8 .. hf*8+7 ----
            #pragma unroll
            for (int n8 = 0; n8 < 8; n8++) {
                int n = hf * 8 + n8;
                int rn = n * 8 + (lane & 7);
                int ko = (lane >> 3) * 8;
                uint32_t bh[8], bl[8];
                LDSM_X4(bh[0], bh[1], bh[2], bh[3], smem_u32(&Kh[rn * KSTR + ko]));
                LDSM_X4(bh[4], bh[5], bh[6], bh[7], smem_u32(&Kh[rn * KSTR + 32 + ko]));
                LDSM_X4(bl[0], bl[1], bl[2], bl[3], smem_u32(&Kl[rn * KSTR + ko]));
                LDSM_X4(bl[4], bl[5], bl[6], bl[7], smem_u32(&Kl[rn * KSTR + 32 + ko]));
                float c1[4] = {0.f, 0.f, 0.f, 0.f};
                float c2[4] = {0.f, 0.f, 0.f, 0.f};
                float c3[4] = {0.f, 0.f, 0.f, 0.f};
                #pragma unroll
                for (int ks = 0; ks < 4; ks++) {
                    MMA_BF16(c1, qh[ks], bh[ks * 2], bh[ks * 2 + 1]);
                    MMA_BF16(c2, qh[ks], bl[ks * 2], bl[ks * 2 + 1]);
                    MMA_BF16(c3, ql[ks], bh[ks * 2], bh[ks * 2 + 1]);
                }
                #pragma unroll
                for (int q = 0; q < 4; q++) cs[n8][q] = c1[q] + c2[q] + c3[q];
            }

            // ---- epilogue: clip, exp, diag, rowsum, write unnormalized E ----
            #pragma unroll
            for (int n8 = 0; n8 < 8; n8++) {
                int gc = jbase + t * 128 + (hf * 8 + n8) * 8 + tc * 2;
                float e0 = __expf(fminf(fmaxf(cs[n8][0], -20.f), 20.f));
                float e1 = __expf(fminf(fmaxf(cs[n8][1], -20.f), 20.f));
                float e2 = __expf(fminf(fmaxf(cs[n8][2], -20.f), 20.f));
                float e3 = __expf(fminf(fmaxf(cs[n8][3], -20.f), 20.f));
                if (gr0 == gc)     e0 = 0.f;
                if (gr0 == gc + 1) e1 = 0.f;
                if (gr1 == gc)     e2 = 0.f;
                if (gr1 == gc + 1) e3 = 0.f;
                rs0 += e0 + e1;
                rs1 += e2 + e3;
                cs[n8][0] = e0; cs[n8][1] = e1; cs[n8][2] = e2; cs[n8][3] = e3;
                *(float2*)&E_out[(size_t)gr0 * N_AGENTS + gc] = make_float2(e0, e1);
                *(float2*)&E_out[(size_t)gr1 * N_AGENTS + gc] = make_float2(e2, e3);
            }

            // ---- attended for kp = 4*hf .. 4*hf+3 ----
            #pragma unroll
            for (int kl = 0; kl < 4; kl++) {
                int kp = 4 * hf + kl;
                uint32_t eh[4], el[4];
                {
                    float s00 = cs[2 * kl][0],     s01 = cs[2 * kl][1];
                    float s10 = cs[2 * kl][2],     s11 = cs[2 * kl][3];
                    float s20 = cs[2 * kl + 1][0], s21 = cs[2 * kl + 1][1];
                    float s30 = cs[2 * kl + 1][2], s31 = cs[2 * kl + 1][3];
                    __nv_bfloat16 h00 = __float2bfloat16(s00), h01 = __float2bfloat16(s01);
                    __nv_bfloat16 h10 = __float2bfloat16(s10), h11 = __float2bfloat16(s11);
                    __nv_bfloat16 h20 = __float2bfloat16(s20), h21 = __float2bfloat16(s21);
                    __nv_bfloat16 h30 = __float2bfloat16(s30), h31 = __float2bfloat16(s31);
                    eh[0] = pack_bf(h00, h01); eh[1] = pack_bf(h10, h11);
                    eh[2] = pack_bf(h20, h21); eh[3] = pack_bf(h30, h31);
                    el[0] = pack_bf(__float2bfloat16(s00 - __bfloat162float(h00)),
                                    __float2bfloat16(s01 - __bfloat162float(h01)));
                    el[1] = pack_bf(__float2bfloat16(s10 - __bfloat162float(h10)),
                                    __float2bfloat16(s11 - __bfloat162float(h11)));
                    el[2] = pack_bf(__float2bfloat16(s20 - __bfloat162float(h20)),
                                    __float2bfloat16(s21 - __bfloat162float(h21)));
                    el[3] = pack_bf(__float2bfloat16(s30 - __bfloat162float(h30)),
                                    __float2bfloat16(s31 - __bfloat162float(h31)));
                }
                #pragma unroll
                for (int g = 0; g < 4; g++) {
                    int rnA = (4 * g + ((lane >> 4) & 1)) * 8 + (lane & 7);
                    int rnB = (4 * g + 2 + ((lane >> 4) & 1)) * 8 + (lane & 7);
                    int jo  = kp * 16 + ((lane >> 3) & 1) * 8;
                    uint32_t mh[8], ml[8];
                    LDSM_X4(mh[0], mh[1], mh[2], mh[3], smem_u32(&Mh[rnA * MSTR + jo]));
                    LDSM_X4(mh[4], mh[5], mh[6], mh[7], smem_u32(&Mh[rnB * MSTR + jo]));
                    LDSM_X4(ml[0], ml[1], ml[2], ml[3], smem_u32(&Ml[rnA * MSTR + jo]));
                    LDSM_X4(ml[4], ml[5], ml[6], ml[7], smem_u32(&Ml[rnB * MSTR + jo]));
                    MMA_BF16(at[4 * g + 0], eh, mh[0], mh[1]);
                    MMA_BF16(at[4 * g + 1], eh, mh[2], mh[3]);
                    MMA_BF16(at[4 * g + 2], eh, mh[4], mh[5]);
                    MMA_BF16(at[4 * g + 3], eh, mh[6], mh[7]);
                    MMA_BF16(at[4 * g + 0], eh, ml[0], ml[1]);
                    MMA_BF16(at[4 * g + 1], eh, ml[2], ml[3]);
                    MMA_BF16(at[4 * g + 2], eh, ml[4], ml[5]);
                    MMA_BF16(at[4 * g + 3], eh, ml[6], ml[7]);
                    MMA_BF16(at[4 * g + 0], el, mh[0], mh[1]);
                    MMA_BF16(at[4 * g + 1], el, mh[2], mh[3]);
                    MMA_BF16(at[4 * g + 2], el, mh[4], mh[5]);
                    MMA_BF16(at[4 * g + 3], el, mh[6], mh[7]);
                }
            }
        }
    }

    rs0 += __shfl_xor_sync(0xFFFFFFFFu, rs0, 1);
    rs0 += __shfl_xor_sync(0xFFFFFFFFu, rs0, 2);
    rs1 += __shfl_xor_sync(0xFFFFFFFFu, rs1, 1);
    rs1 += __shfl_xor_sync(0xFFFFFFFFu, rs1, 2);
    if (tc == 0) {
        g_S_part[(size_t)blockIdx.y * N_AGENTS + gr0] = rs0;
        g_S_part[(size_t)blockIdx.y * N_AGENTS + gr1] = rs1;
    }

    #pragma unroll
    for (int n = 0; n < 16; n++) {
        size_t b0 = ((size_t)blockIdx.y * N_AGENTS + gr0) * MSG + n * 8 + tc * 2;
        size_t b1 = ((size_t)blockIdx.y * N_AGENTS + gr1) * MSG + n * 8 + tc * 2;
        *(float2*)&g_att_part[b0] = make_float2(at[n][0], at[n][1]);
        *(float2*)&g_att_part[b1] = make_float2(at[n][2], at[n][3]);
    }
}

// ---------------- tensor-core GEMM: tile 128x64, 2 blocks/SM ----------------
#define GSTR 72
#define G_AL (128 * GSTR)
#define G_BH (2 * 128 * GSTR)
#define G_BL (2 * 128 * GSTR + 64 * GSTR)
#define GEMM_SMEM ((2 * 128 * GSTR + 2 * 64 * GSTR) * 2)   // 55296 bytes

__global__ __launch_bounds__(256, 2) void gemm_tc(
    const __nv_bfloat16* __restrict__ Ah, const __nv_bfloat16* __restrict__ Al,
    const __nv_bfloat16* __restrict__ Bh, const __nv_bfloat16* __restrict__ Bl,
    const float* __restrict__ bias, float* __restrict__ C, int K, int N)
{
    extern __shared__ __nv_bfloat16 gsm[];

    const int tid = threadIdx.x, w = tid >> 5, lane = tid & 31;
    const int tr = lane >> 2, tc = lane & 3;
    const int row0 = w * 16;
    const int m0 = blockIdx.y * 128, n0 = blockIdx.x * 64;

    float at[8][4];
    #pragma unroll
    for (int n = 0; n < 8; n++)
        #pragma unroll
        for (int q = 0; q < 4; q++) at[n][q] = 0.f;

    for (int kc = 0; kc < K; kc += 64) {
        __syncthreads();
        #pragma unroll
        for (int it = 0; it < 4; it++) {
            int idx = tid + it * 256;
            int r = idx >> 3, ch = idx & 7;
            *(uint4*)&gsm[r * GSTR + ch * 8] =
                *(const uint4*)&Ah[(size_t)(m0 + r) * K + kc + ch * 8];
            *(uint4*)&gsm[G_AL + r * GSTR + ch * 8] =
                *(const uint4*)&Al[(size_t)(m0 + r) * K + kc + ch * 8];
        }
        #pragma unroll
        for (int it = 0; it < 2; it++) {
            int idx = tid + it * 256;
            int r = idx >> 3, ch = idx & 7;
            *(uint4*)&gsm[G_BH + r * GSTR + ch * 8] =
                *(const uint4*)&Bh[(size_t)(n0 + r) * K + kc + ch * 8];
            *(uint4*)&gsm[G_BL + r * GSTR + ch * 8] =
                *(const uint4*)&Bl[(size_t)(n0 + r) * K + kc + ch * 8];
        }
        __syncthreads();

        uint32_t ah[4][4], al[4][4];
        {
            int octet = lane >> 3;
            int rr = row0 + (octet & 1) * 8 + (lane & 7);
            int kk = (octet >> 1) * 8;
            #pragma unroll
            for (int ks = 0; ks < 4; ks++) {
                LDSM_X4(ah[ks][0], ah[ks][1], ah[ks][2], ah[ks][3],
                        smem_u32(&gsm[rr * GSTR + ks * 16 + kk]));
                LDSM_X4(al[ks][0], al[ks][1], al[ks][2], al[ks][3],
                        smem_u32(&gsm[G_AL + rr * GSTR + ks * 16 + kk]));
            }
        }
        #pragma unroll
        for (int g = 0; g < 2; g++) {
            int rnA = 32 * g + ((lane >> 4) & 1) * 8 + (lane & 7);
            int rnB = rnA + 16;
            int ko = ((lane >> 3) & 1) * 8;
            #pragma unroll
            for (int ks = 0; ks < 4; ks++) {
                uint32_t bhA[4], blA[4], bhB[4], blB[4];
                LDSM_X4(bhA[0], bhA[1], bhA[2], bhA[3],
                        smem_u32(&gsm[G_BH + rnA * GSTR + ks * 16 + ko]));
                LDSM_X4(blA[0], blA[1], blA[2], blA[3],
                        smem_u32(&gsm[G_BL + rnA * GSTR + ks * 16 + ko]));
                LDSM_X4(bhB[0], bhB[1], bhB[2], bhB[3],
                        smem_u32(&gsm[G_BH + rnB * GSTR + ks * 16 + ko]));
                LDSM_X4(blB[0], blB[1], blB[2], blB[3],
                        smem_u32(&gsm[G_BL + rnB * GSTR + ks * 16 + ko]));
                MMA_BF16(at[4 * g + 0], ah[ks], bhA[0], bhA[1]);
                MMA_BF16(at[4 * g + 1], ah[ks], bhA[2], bhA[3]);
                MMA_BF16(at[4 * g + 2], ah[ks], bhB[0], bhB[1]);
                MMA_BF16(at[4 * g + 3], ah[ks], bhB[2], bhB[3]);
                MMA_BF16(at[4 * g + 0], ah[ks], blA[0], blA[1]);
                MMA_BF16(at[4 * g + 1], ah[ks], blA[2], blA[3]);
                MMA_BF16(at[4 * g + 2], ah[ks], blB[0], blB[1]);
                MMA_BF16(at[4 * g + 3], ah[ks], blB[2], blB[3]);
                MMA_BF16(at[4 * g + 0], al[ks], bhA[0], bhA[1]);
                MMA_BF16(at[4 * g + 1], al[ks], bhA[2], bhA[3]);
                MMA_BF16(at[4 * g + 2], al[ks], bhB[0], bhB[1]);
                MMA_BF16(at[4 * g + 3], al[ks], bhB[2], bhB[3]);
            }
        }
    }

    const int gr0 = m0 + row0 + tr, gr1 = gr0 + 8;
    #pragma unroll
    for (int n = 0; n < 8; n++) {
        int col = n0 + n * 8 + tc * 2;
        float b0 = bias ? bias[col] : 0.f;
        float b1 = bias ? bias[col + 1] : 0.f;
        *(float2*)&C[(size_t)gr0 * N + col] = make_float2(at[n][0] + b0, at[n][1] + b1);
        *(float2*)&C[(size_t)gr1 * N + col] = make_float2(at[n][2] + b0, at[n][3] + b1);
    }
}

// ---------------- prep kernels ----------------
__global__ void h_split_kernel(const float* __restrict__ h)
{
    int v = blockIdx.x * blockDim.x + threadIdx.x;
    float4 a = ((const float4*)h)[v];
    __nv_bfloat16 h0 = __float2bfloat16(a.x), h1 = __float2bfloat16(a.y);
    __nv_bfloat16 h2 = __float2bfloat16(a.z), h3 = __float2bfloat16(a.w);
    *(uint2*)&g_hh[4 * v] = make_uint2(pack_bf(h0, h1), pack_bf(h2, h3));
    *(uint2*)&g_hl[4 * v] = make_uint2(
        pack_bf(__float2bfloat16(a.x - __bfloat162float(h0)),
                __float2bfloat16(a.y - __bfloat162float(h1))),
        pack_bf(__float2bfloat16(a.z - __bfloat162float(h2)),
                __float2bfloat16(a.w - __bfloat162float(h3))));
}

struct WEnt { const float* src; int N, row_off, Kd, start, count, dst; float scale; };
struct WAll { WEnt w[9]; int total; };

__global__ void prep_weights_kernel(WAll a)
{
    int idx = blockIdx.x * blockDim.x + threadIdx.x;
    if (idx >= a.total) return;
    #pragma unroll
    for (int e = 0; e < 9; e++) {
        if (idx >= a.w[e].start && idx < a.w[e].start + a.w[e].count) {
            int li = idx - a.w[e].start;
            int k = li / a.w[e].N, n = li % a.w[e].N;
            float v = a.w[e].src[li] * a.w[e].scale;
            __nv_bfloat16 hi = __float2bfloat16(v);
            __nv_bfloat16 lo = __float2bfloat16(v - __bfloat162float(hi));
            size_t o = (size_t)(a.w[e].row_off + n) * a.w[e].Kd + k;
            if (a.w[e].dst == 0)      { g_Wp_h[o] = hi; g_Wp_l[o] = lo; }
            else if (a.w[e].dst == 1) { g_Wi_h[o] = hi; g_Wi_l[o] = lo; }
            else                      { g_Wh_h[o] = hi; g_Wh_l[o] = lo; }
            return;
        }
    }
}

__global__ void bias_cat_kernel(const float* b_msg, const float* b_key, const float* b_qry,
                                const float* bi_r, const float* bi_z, const float* bi_n)
{
    int i = threadIdx.x;
    if (i < 128)      g_bias_p[i] = b_msg[i];
    else if (i < 192) g_bias_p[i] = b_key[i - 128];
    else if (i < 256) g_bias_p[i] = 0.125f * b_qry[i - 192];
    if (i < 256)      g_bias_i[i] = bi_r[i];
    else if (i < 512) g_bias_i[i] = bi_z[i - 256];
    else if (i < 768) g_bias_i[i] = bi_n[i - 512];
}

__global__ void split_qk_kernel()
{
    int i = blockIdx.x * blockDim.x + threadIdx.x;
    int row = i >> 6, c = i & 63;
    float k = g_qkm[(size_t)row * 256 + 128 + c];
    __nv_bfloat16 kh = __float2bfloat16(k);
    g_kh[i] = kh; g_kl[i] = __float2bfloat16(k - __bfloat162float(kh));
    float q = g_qkm[(size_t)row * 256 + 192 + c];
    __nv_bfloat16 qh = __float2bfloat16(q);
    g_qh[i] = qh; g_ql[i] = __float2bfloat16(q - __bfloat162float(qh));
}

__global__ void msgT_split_kernel()
{
    __shared__ float t[32][33];
    int n0 = blockIdx.x * 32, m0 = blockIdx.y * 32;
    #pragma unroll
    for (int i = threadIdx.y; i < 32; i += 8)
        t[i][threadIdx.x] = g_qkm[(size_t)(n0 + i) * 256 + m0 + threadIdx.x];
    __syncthreads();
    #pragma unroll
    for (int i = threadIdx.y; i < 32; i += 8) {
        float v = t[threadIdx.x][i];
        __nv_bfloat16 hi = __float2bfloat16(v);
        size_t o = (size_t)(m0 + i) * N_AGENTS + n0 + threadIdx.x;
        g_mTh[o] = hi;
        g_mTl[o] = __float2bfloat16(v - __bfloat162float(hi));
    }
}

// ---------------- normalization / epilogue kernels ----------------
__global__ void inv_S_kernel()
{
    int i = blockIdx.x * blockDim.x + threadIdx.x;
    g_S[i] = 1.0f / (g_S_part[i] + g_S_part[N_AGENTS + i]
                   + g_S_part[2 * N_AGENTS + i] + g_S_part[3 * N_AGENTS + i]);
}

__global__ void norm_attended_kernel()
{
    int v = blockIdx.x * blockDim.x + threadIdx.x;
    float inv = g_S[v >> 5];
    const size_t stride = (size_t)N_AGENTS * MSG / 4;
    float4 a = ((const float4*)g_att_part)[v];
    float4 b = ((const float4*)g_att_part)[v + stride];
    float4 c = ((const float4*)g_att_part)[v + 2 * stride];
    float4 d = ((const float4*)g_att_part)[v + 3 * stride];
    float4 o = make_float4((a.x + b.x + c.x + d.x) * inv,
                           (a.y + b.y + c.y + d.y) * inv,
                           (a.z + b.z + c.z + d.z) * inv,
                           (a.w + b.w + c.w + d.w) * inv);
    __nv_bfloat16 h0 = __float2bfloat16(o.x), h1 = __float2bfloat16(o.y);
    __nv_bfloat16 h2 = __float2bfloat16(o.z), h3 = __float2bfloat16(o.w);
    *(uint2*)&g_ath[4 * v] = make_uint2(pack_bf(h0, h1), pack_bf(h2, h3));
    *(uint2*)&g_atl[4 * v] = make_uint2(
        pack_bf(__float2bfloat16(o.x - __bfloat162float(h0)),
                __float2bfloat16(o.y - __bfloat162float(h1))),
        pack_bf(__float2bfloat16(o.z - __bfloat162float(h2)),
                __float2bfloat16(o.w - __bfloat162float(h3))));
}

__global__ void norm_attn_kernel(float* __restrict__ E)
{
    int v = blockIdx.x * blockDim.x + threadIdx.x;
    float inv = g_S[v >> 11];
    float4 a = ((const float4*)E)[v];
    a.x *= inv; a.y *= inv; a.z *= inv; a.w *= inv;
    ((float4*)E)[v] = a;
}

__device__ __forceinline__ float sigm(float x) { return 1.f / (1.f + __expf(-x)); }

__global__ void gru_final_kernel(const float* __restrict__ h,
                                 const float* __restrict__ bh_n,
                                 float* __restrict__ out)
{
    int v = blockIdx.x * blockDim.x + threadIdx.x;
    int row = v >> 6, c4 = (v & 63) * 4;
    const float* GA = g_GA + (size_t)row * 768;
    const float* GB = g_GB + (size_t)row * 768;
    float4 gar = *(const float4*)&GA[c4];
    float4 gaz = *(const float4*)&GA[256 + c4];
    float4 gan = *(const float4*)&GA[512 + c4];
    float4 gbr = *(const float4*)&GB[c4];
    float4 gbz = *(const float4*)&GB[256 + c4];
    float4 gbn = *(const float4*)&GB[512 + c4];
    float4 bn  = *(const float4*)&bh_n[c4];
    float4 hh  = ((const float4*)h)[v];
    float4 o;
    { float r = sigm(gar.x + gbr.x), z = sigm(gaz.x + gbz.x);
      float n = tanhf(gan.x + r * (gbn.x + bn.x)); o.x = (1.f - z) * n + z * hh.x; }
    { float r = sigm(gar.y + gbr.y), z = sigm(gaz.y + gbz.y);
      float n = tanhf(gan.y + r * (gbn.y + bn.y)); o.y = (1.f - z) * n + z * hh.y; }
    { float r = sigm(gar.z + gbr.z), z = sigm(gaz.z + gbz.z);
      float n = tanhf(gan.z + r * (gbn.z + bn.z)); o.z = (1.f - z) * n + z * hh.z; }
    { float r = sigm(gar.w + gbr.w), z = sigm(gaz.w + gbz.w);
      float n = tanhf(gan.w + r * (gbn.w + bn.w)); o.w = (1.f - z) * n + z * hh.w; }
    ((float4*)out)[v] = o;
}

// ---------------- launch ----------------
extern "C" void kernel_launch(void* const* d_in, const int* in_sizes, int n_in,
                              void* d_out, int out_size)
{
    const float* h     = (const float*)d_in[0];
    const float* W_msg = (const float*)d_in[1];
    const float* b_msg = (const float*)d_in[2];
    const float* W_key = (const float*)d_in[3];
    const float* b_key = (const float*)d_in[4];
    const float* W_qry = (const float*)d_in[5];
    const float* b_qry = (const float*)d_in[6];
    const float* Wi_r  = (const float*)d_in[7];
    const float* bi_r  = (const float*)d_in[8];
    const float* Wi_z  = (const float*)d_in[9];
    const float* bi_z  = (const float*)d_in[10];
    const float* Wi_n  = (const float*)d_in[11];
    const float* bi_n  = (const float*)d_in[12];
    const float* Wh_r  = (const float*)d_in[13];
    const float* Wh_z  = (const float*)d_in[14];
    const float* Wh_n  = (const float*)d_in[15];
    const float* bh_n  = (const float*)d_in[16];

    float* out    = (float*)d_out;
    float* h_new  = out;
    float* attn   = out + (size_t)N_AGENTS * HIDDEN;

    float *p_qkm, *p_GA, *p_GB, *p_bias_p, *p_bias_i;
    __nv_bfloat16 *p_hh, *p_hl, *p_ath, *p_atl;
    __nv_bfloat16 *p_Wp_h, *p_Wp_l, *p_Wi_h, *p_Wi_l, *p_Wh_h, *p_Wh_l;
    cudaGetSymbolAddress((void**)&p_qkm, g_qkm);
    cudaGetSymbolAddress((void**)&p_GA, g_GA);
    cudaGetSymbolAddress((void**)&p_GB, g_GB);
    cudaGetSymbolAddress((void**)&p_bias_p, g_bias_p);
    cudaGetSymbolAddress((void**)&p_bias_i, g_bias_i);
    cudaGetSymbolAddress((void**)&p_hh, g_hh);
    cudaGetSymbolAddress((void**)&p_hl, g_hl);
    cudaGetSymbolAddress((void**)&p_ath, g_ath);
    cudaGetSymbolAddress((void**)&p_atl, g_atl);
    cudaGetSymbolAddress((void**)&p_Wp_h, g_Wp_h);
    cudaGetSymbolAddress((void**)&p_Wp_l, g_Wp_l);
    cudaGetSymbolAddress((void**)&p_Wi_h, g_Wi_h);
    cudaGetSymbolAddress((void**)&p_Wi_l, g_Wi_l);
    cudaGetSymbolAddress((void**)&p_Wh_h, g_Wh_h);
    cudaGetSymbolAddress((void**)&p_Wh_l, g_Wh_l);

    cudaFuncSetAttribute(attn_mma_kernel, cudaFuncAttributeMaxDynamicSharedMemorySize, ATTN_SMEM);
    cudaFuncSetAttribute(gemm_tc, cudaFuncAttributeMaxDynamicSharedMemorySize, GEMM_SMEM);

    WAll wa;
    int off = 0;
    auto add = [&](int e, const float* src, int K, int N, int row_off, int Kd, int dst, float sc) {
        wa.w[e] = WEnt{src, N, row_off, Kd, off, K * N, dst, sc};
        off += K * N;
    };
    add(0, W_msg, 256, 128, 0,   256, 0, 1.0f);
    add(1, W_key, 256, 64,  128, 256, 0, 1.0f);
    add(2, W_qry, 256, 64,  192, 256, 0, 0.125f);
    add(3, Wi_r,  128, 256, 0,   128, 1, 1.0f);
    add(4, Wi_z,  128, 256, 256, 128, 1, 1.0f);
    add(5, Wi_n,  128, 256, 512, 128, 1, 1.0f);
    add(6, Wh_r,  256, 256, 0,   256, 2, 1.0f);
    add(7, Wh_z,  256, 256, 256, 256, 2, 1.0f);
    add(8, Wh_n,  256, 256, 512, 256, 2, 1.0f);
    wa.total = off;

    h_split_kernel<<<(N_AGENTS * HIDDEN / 4) / 256, 256>>>(h);
    bias_cat_kernel<<<1, 1024>>>(b_msg, b_key, b_qry, bi_r, bi_z, bi_n);
    prep_weights_kernel<<<(wa.total + 255) / 256, 256>>>(wa);

    // fused projection: qkm = h @ [W_msg | W_key | 0.125*W_qry] + bias
    gemm_tc<<<dim3(4, N_AGENTS / 128), 256, GEMM_SMEM>>>(
        p_hh, p_hl, p_Wp_h, p_Wp_l, p_bias_p, p_qkm, 256, 256);
    split_qk_kernel<<<(N_AGENTS * KEY) / 256, 256>>>();
    msgT_split_kernel<<<dim3(N_AGENTS / 32, MSG / 32), dim3(32, 8)>>>();

    // fused tensor-core attention (2 blocks/SM)
    attn_mma_kernel<<<dim3(N_AGENTS / 128, NSPLIT), 256, ATTN_SMEM>>>(attn);

    inv_S_kernel<<<N_AGENTS / 256, 256>>>();
    norm_attended_kernel<<<(N_AGENTS * MSG / 4) / 256, 256>>>();
    norm_attn_kernel<<<(int)(((size_t)N_AGENTS * N_AGENTS / 4) / 256), 256>>>(attn);

    // GRU gates
    gemm_tc<<<dim3(12, N_AGENTS / 128), 256, GEMM_SMEM>>>(
        p_ath, p_atl, p_Wi_h, p_Wi_l, p_bias_i, p_GA, 128, 768);
    gemm_tc<<<dim3(12, N_AGENTS / 128), 256, GEMM_SMEM>>>(
        p_hh, p_hl, p_Wh_h, p_Wh_l, nullptr, p_GB, 256, 768);

    gru_final_kernel<<<(N_AGENTS * HIDDEN / 4) / 256, 256>>>(h, bh_n, h_new);
}

// round 10
// speedup vs baseline: 1.0978x; 1.0978x over previous
#include <cuda_runtime.h>
#include <cuda_bf16.h>
#include <cstddef>
#include <cstdint>

#define N_AGENTS 8192
#define HIDDEN   256
#define MSG      128
#define KEY      64
#define NSPLIT   2
#define COLS_PER_SPLIT (N_AGENTS / NSPLIT)   // 4096
#define NT (COLS_PER_SPLIT / 128)            // 32 j-tiles per block

// ---------------- scratch (no allocations allowed) ----------------
__device__ float g_qkm[N_AGENTS * 256];
__device__ float g_S  [N_AGENTS];
__device__ float g_S_part[NSPLIT * N_AGENTS];
__device__ float g_att_part[NSPLIT * N_AGENTS * MSG];
__device__ float g_GA[N_AGENTS * 768];
__device__ float g_GB[N_AGENTS * 768];
__device__ float g_bias_p[256];
__device__ float g_bias_i[768];

__device__ __align__(16) __nv_bfloat16 g_kh[N_AGENTS * KEY];
__device__ __align__(16) __nv_bfloat16 g_kl[N_AGENTS * KEY];
__device__ __align__(16) __nv_bfloat16 g_qh[N_AGENTS * KEY];   // prescaled by 1/8
__device__ __align__(16) __nv_bfloat16 g_ql[N_AGENTS * KEY];
__device__ __align__(16) __nv_bfloat16 g_mTh[MSG * N_AGENTS];
__device__ __align__(16) __nv_bfloat16 g_mTl[MSG * N_AGENTS];
__device__ __align__(16) __nv_bfloat16 g_hh[N_AGENTS * HIDDEN];
__device__ __align__(16) __nv_bfloat16 g_hl[N_AGENTS * HIDDEN];
__device__ __align__(16) __nv_bfloat16 g_ath[N_AGENTS * MSG];
__device__ __align__(16) __nv_bfloat16 g_atl[N_AGENTS * MSG];
__device__ __align__(16) __nv_bfloat16 g_Wp_h[256 * 256];
__device__ __align__(16) __nv_bfloat16 g_Wp_l[256 * 256];
__device__ __align__(16) __nv_bfloat16 g_Wi_h[768 * 128];
__device__ __align__(16) __nv_bfloat16 g_Wi_l[768 * 128];
__device__ __align__(16) __nv_bfloat16 g_Wh_h[768 * 256];
__device__ __align__(16) __nv_bfloat16 g_Wh_l[768 * 256];

// ---------------- PTX helpers (compute_103-safe) ----------------
__device__ __forceinline__ uint32_t smem_u32(const void* p) {
    uint32_t a;
    asm("{ .reg .u64 t; cvta.to.shared.u64 t, %1; cvt.u32.u64 %0, t; }" : "=r"(a) : "l"(p));
    return a;
}

#define LDSM_X4(r0, r1, r2, r3, addr) \
    asm volatile("ldmatrix.sync.aligned.m8n8.x4.shared.b16 {%0,%1,%2,%3}, [%4];" \
                 : "=r"(r0), "=r"(r1), "=r"(r2), "=r"(r3) : "r"(addr))

#define MMA_BF16(C, A, B0, B1) \
    asm volatile("mma.sync.aligned.m16n8k16.row.col.f32.bf16.bf16.f32 " \
                 "{%0,%1,%2,%3}, {%4,%5,%6,%7}, {%8,%9}, {%0,%1,%2,%3};" \
                 : "+f"((C)[0]), "+f"((C)[1]), "+f"((C)[2]), "+f"((C)[3]) \
                 : "r"((A)[0]), "r"((A)[1]), "r"((A)[2]), "r"((A)[3]), \
                   "r"(B0), "r"(B1))

#define CP16(smaddr, gptr) \
    asm volatile("cp.async.cg.shared.global [%0], [%1], 16;" :: "r"(smaddr), "l"(gptr) : "memory")
#define CP_COMMIT asm volatile("cp.async.commit_group;" ::: "memory")
#define CP_WAIT1  asm volatile("cp.async.wait_group 1;" ::: "memory")

__device__ __forceinline__ uint32_t pack_bf(__nv_bfloat16 a, __nv_bfloat16 b) {
    return (uint32_t)__bfloat16_as_ushort(a) | ((uint32_t)__bfloat16_as_ushort(b) << 16);
}

// ---------------- attention smem layout (2 pipeline stages) ----------------
#define KSTR 72
#define MSTR 136
#define S_KL (128 * KSTR)
#define S_MH (2 * 128 * KSTR)
#define S_ML (S_MH + 128 * MSTR)
#define STAGE_ELEMS (2 * 128 * KSTR + 2 * 128 * MSTR)   // 53248 bf16
#define ATTN_SMEM (2 * STAGE_ELEMS * 2)                 // 212992 bytes

__device__ __forceinline__ void issue_tile(__nv_bfloat16* stage, size_t j0, int tid) {
    __nv_bfloat16* Kh = stage;
    __nv_bfloat16* Kl = stage + S_KL;
    __nv_bfloat16* Mh = stage + S_MH;
    __nv_bfloat16* Ml = stage + S_ML;
    #pragma unroll
    for (int it = 0; it < 4; it++) {
        int idx = tid + it * 256;
        int r = idx >> 3, ch = idx & 7;
        CP16(smem_u32(&Kh[r * KSTR + ch * 8]), &g_kh[(j0 + r) * KEY + ch * 8]);
        CP16(smem_u32(&Kl[r * KSTR + ch * 8]), &g_kl[(j0 + r) * KEY + ch * 8]);
    }
    #pragma unroll
    for (int it = 0; it < 8; it++) {
        int idx = tid + it * 256;
        int c = idx >> 4, ch = idx & 15;
        CP16(smem_u32(&Mh[c * MSTR + ch * 8]), &g_mTh[(size_t)c * N_AGENTS + j0 + ch * 8]);
        CP16(smem_u32(&Ml[c * MSTR + ch * 8]), &g_mTl[(size_t)c * N_AGENTS + j0 + ch * 8]);
    }
}

// ---------------- fused attention: mma.sync, chain-broken (R8 proven) ----------------
__global__ __launch_bounds__(256, 1) void attn_mma_kernel(float* __restrict__ E_out)
{
    extern __shared__ __nv_bfloat16 sm[];
    __nv_bfloat16* st0 = sm;
    __nv_bfloat16* st1 = sm + STAGE_ELEMS;

    const int tid  = threadIdx.x;
    const int w    = tid >> 5, lane = tid & 31;
    const int tr   = lane >> 2;
    const int tc   = lane & 3;
    const int row0 = w * 16;
    const int i0    = blockIdx.x * 128;
    const int jbase = blockIdx.y * COLS_PER_SPLIT;

    #pragma unroll
    for (int it = 0; it < 4; it++) {
        int idx = tid + it * 256;
        int r = idx >> 3, ch = idx & 7;
        *(uint4*)&st0[r * KSTR + ch * 8] =
            *(const uint4*)&g_qh[(size_t)(i0 + r) * KEY + ch * 8];
        *(uint4*)&st0[S_KL + r * KSTR + ch * 8] =
            *(const uint4*)&g_ql[(size_t)(i0 + r) * KEY + ch * 8];
    }
    __syncthreads();

    uint32_t qh[4][4], ql[4][4];
    {
        int octet = lane >> 3;
        int rr = row0 + (octet & 1) * 8 + (lane & 7);
        int kk = (octet >> 1) * 8;
        #pragma unroll
        for (int ks = 0; ks < 4; ks++) {
            LDSM_X4(qh[ks][0], qh[ks][1], qh[ks][2], qh[ks][3],
                    smem_u32(&st0[rr * KSTR + ks * 16 + kk]));
            LDSM_X4(ql[ks][0], ql[ks][1], ql[ks][2], ql[ks][3],
                    smem_u32(&st0[S_KL + rr * KSTR + ks * 16 + kk]));
        }
    }
    __syncthreads();

    issue_tile(st0, (size_t)jbase, tid);       CP_COMMIT;
    issue_tile(st1, (size_t)jbase + 128, tid); CP_COMMIT;

    float at[16][4];
    #pragma unroll
    for (int n = 0; n < 16; n++)
        #pragma unroll
        for (int q = 0; q < 4; q++) at[n][q] = 0.f;
    float rs0 = 0.f, rs1 = 0.f;

    const int gr0 = i0 + row0 + tr;
    const int gr1 = gr0 + 8;

    for (int t = 0; t < NT; t++) {
        CP_WAIT1;
        __syncthreads();
        __nv_bfloat16* stage = (t & 1) ? st1 : st0;
        __nv_bfloat16* Kh = stage;
        __nv_bfloat16* Kl = stage + S_KL;
        __nv_bfloat16* Mh = stage + S_MH;
        __nv_bfloat16* Ml = stage + S_ML;
        const int jt = t * 128;

        // ---- scores: 3 independent accumulator chains per n-tile ----
        float cs[16][4];
        #pragma unroll
        for (int n = 0; n < 16; n++) {
            int rn = n * 8 + (lane & 7);
            int ko = (lane >> 3) * 8;
            uint32_t bh[8], bl[8];
            LDSM_X4(bh[0], bh[1], bh[2], bh[3], smem_u32(&Kh[rn * KSTR + ko]));
            LDSM_X4(bh[4], bh[5], bh[6], bh[7], smem_u32(&Kh[rn * KSTR + 32 + ko]));
            LDSM_X4(bl[0], bl[1], bl[2], bl[3], smem_u32(&Kl[rn * KSTR + ko]));
            LDSM_X4(bl[4], bl[5], bl[6], bl[7], smem_u32(&Kl[rn * KSTR + 32 + ko]));
            float c1[4] = {0.f, 0.f, 0.f, 0.f};
            float c2[4] = {0.f, 0.f, 0.f, 0.f};
            float c3[4] = {0.f, 0.f, 0.f, 0.f};
            #pragma unroll
            for (int ks = 0; ks < 4; ks++) {
                MMA_BF16(c1, qh[ks], bh[ks * 2], bh[ks * 2 + 1]);
                MMA_BF16(c2, qh[ks], bl[ks * 2], bl[ks * 2 + 1]);
                MMA_BF16(c3, ql[ks], bh[ks * 2], bh[ks * 2 + 1]);
            }
            #pragma unroll
            for (int q = 0; q < 4; q++) cs[n][q] = c1[q] + c2[q] + c3[q];
        }

        // ---- epilogue: clip, exp, diag, rowsum, write unnormalized E ----
        #pragma unroll
        for (int n = 0; n < 16; n++) {
            int gc = jbase + jt + n * 8 + tc * 2;
            float e0 = __expf(fminf(fmaxf(cs[n][0], -20.f), 20.f));
            float e1 = __expf(fminf(fmaxf(cs[n][1], -20.f), 20.f));
            float e2 = __expf(fminf(fmaxf(cs[n][2], -20.f), 20.f));
            float e3 = __expf(fminf(fmaxf(cs[n][3], -20.f), 20.f));
            if (gr0 == gc)     e0 = 0.f;
            if (gr0 == gc + 1) e1 = 0.f;
            if (gr1 == gc)     e2 = 0.f;
            if (gr1 == gc + 1) e3 = 0.f;
            rs0 += e0 + e1;
            rs1 += e2 + e3;
            cs[n][0] = e0; cs[n][1] = e1; cs[n][2] = e2; cs[n][3] = e3;
            *(float2*)&E_out[(size_t)gr0 * N_AGENTS + gc] = make_float2(e0, e1);
            *(float2*)&E_out[(size_t)gr1 * N_AGENTS + gc] = make_float2(e2, e3);
        }

        // ---- attended: 4-wide n groups, product-major (distance-4 chains) ----
        #pragma unroll
        for (int kp = 0; kp < 8; kp++) {
            uint32_t eh[4], el[4];
            {
                float s00 = cs[2 * kp][0],     s01 = cs[2 * kp][1];
                float s10 = cs[2 * kp][2],     s11 = cs[2 * kp][3];
                float s20 = cs[2 * kp + 1][0], s21 = cs[2 * kp + 1][1];
                float s30 = cs[2 * kp + 1][2], s31 = cs[2 * kp + 1][3];
                __nv_bfloat16 h00 = __float2bfloat16(s00), h01 = __float2bfloat16(s01);
                __nv_bfloat16 h10 = __float2bfloat16(s10), h11 = __float2bfloat16(s11);
                __nv_bfloat16 h20 = __float2bfloat16(s20), h21 = __float2bfloat16(s21);
                __nv_bfloat16 h30 = __float2bfloat16(s30), h31 = __float2bfloat16(s31);
                eh[0] = pack_bf(h00, h01); eh[1] = pack_bf(h10, h11);
                eh[2] = pack_bf(h20, h21); eh[3] = pack_bf(h30, h31);
                el[0] = pack_bf(__float2bfloat16(s00 - __bfloat162float(h00)),
                                __float2bfloat16(s01 - __bfloat162float(h01)));
                el[1] = pack_bf(__float2bfloat16(s10 - __bfloat162float(h10)),
                                __float2bfloat16(s11 - __bfloat162float(h11)));
                el[2] = pack_bf(__float2bfloat16(s20 - __bfloat162float(h20)),
                                __float2bfloat16(s21 - __bfloat162float(h21)));
                el[3] = pack_bf(__float2bfloat16(s30 - __bfloat162float(h30)),
                                __float2bfloat16(s31 - __bfloat162float(h31)));
            }
            #pragma unroll
            for (int g = 0; g < 4; g++) {
                int rnA = (4 * g + ((lane >> 4) & 1)) * 8 + (lane & 7);
                int rnB = (4 * g + 2 + ((lane >> 4) & 1)) * 8 + (lane & 7);
                int jo  = kp * 16 + ((lane >> 3) & 1) * 8;
                uint32_t mh[8], ml[8];
                LDSM_X4(mh[0], mh[1], mh[2], mh[3], smem_u32(&Mh[rnA * MSTR + jo]));
                LDSM_X4(mh[4], mh[5], mh[6], mh[7], smem_u32(&Mh[rnB * MSTR + jo]));
                LDSM_X4(ml[0], ml[1], ml[2], ml[3], smem_u32(&Ml[rnA * MSTR + jo]));
                LDSM_X4(ml[4], ml[5], ml[6], ml[7], smem_u32(&Ml[rnB * MSTR + jo]));
                MMA_BF16(at[4 * g + 0], eh, mh[0], mh[1]);
                MMA_BF16(at[4 * g + 1], eh, mh[2], mh[3]);
                MMA_BF16(at[4 * g + 2], eh, mh[4], mh[5]);
                MMA_BF16(at[4 * g + 3], eh, mh[6], mh[7]);
                MMA_BF16(at[4 * g + 0], eh, ml[0], ml[1]);
                MMA_BF16(at[4 * g + 1], eh, ml[2], ml[3]);
                MMA_BF16(at[4 * g + 2], eh, ml[4], ml[5]);
                MMA_BF16(at[4 * g + 3], eh, ml[6], ml[7]);
                MMA_BF16(at[4 * g + 0], el, mh[0], mh[1]);
                MMA_BF16(at[4 * g + 1], el, mh[2], mh[3]);
                MMA_BF16(at[4 * g + 2], el, mh[4], mh[5]);
                MMA_BF16(at[4 * g + 3], el, mh[6], mh[7]);
            }
        }

        __syncthreads();
        if (t + 2 < NT)
            issue_tile((t & 1) ? st1 : st0, (size_t)jbase + (size_t)(t + 2) * 128, tid);
        CP_COMMIT;
    }

    rs0 += __shfl_xor_sync(0xFFFFFFFFu, rs0, 1);
    rs0 += __shfl_xor_sync(0xFFFFFFFFu, rs0, 2);
    rs1 += __shfl_xor_sync(0xFFFFFFFFu, rs1, 1);
    rs1 += __shfl_xor_sync(0xFFFFFFFFu, rs1, 2);
    if (tc == 0) {
        g_S_part[(size_t)blockIdx.y * N_AGENTS + gr0] = rs0;
        g_S_part[(size_t)blockIdx.y * N_AGENTS + gr1] = rs1;
    }

    #pragma unroll
    for (int n = 0; n < 16; n++) {
        size_t b0 = ((size_t)blockIdx.y * N_AGENTS + gr0) * MSG + n * 8 + tc * 2;
        size_t b1 = ((size_t)blockIdx.y * N_AGENTS + gr1) * MSG + n * 8 + tc * 2;
        *(float2*)&g_att_part[b0] = make_float2(at[n][0], at[n][1]);
        *(float2*)&g_att_part[b1] = make_float2(at[n][2], at[n][3]);
    }
}

// ---------------- tensor-core GEMM: tile 128x64, 2 blocks/SM (R9 proven) ----------------
#define GSTR 72
#define G_AL (128 * GSTR)
#define G_BH (2 * 128 * GSTR)
#define G_BL (2 * 128 * GSTR + 64 * GSTR)
#define GEMM_SMEM ((2 * 128 * GSTR + 2 * 64 * GSTR) * 2)   // 55296 bytes

__global__ __launch_bounds__(256, 2) void gemm_tc(
    const __nv_bfloat16* __restrict__ Ah, const __nv_bfloat16* __restrict__ Al,
    const __nv_bfloat16* __restrict__ Bh, const __nv_bfloat16* __restrict__ Bl,
    const float* __restrict__ bias, float* __restrict__ C, int K, int N)
{
    extern __shared__ __nv_bfloat16 gsm[];

    const int tid = threadIdx.x, w = tid >> 5, lane = tid & 31;
    const int tr = lane >> 2, tc = lane & 3;
    const int row0 = w * 16;
    const int m0 = blockIdx.y * 128, n0 = blockIdx.x * 64;

    float at[8][4];
    #pragma unroll
    for (int n = 0; n < 8; n++)
        #pragma unroll
        for (int q = 0; q < 4; q++) at[n][q] = 0.f;

    for (int kc = 0; kc < K; kc += 64) {
        __syncthreads();
        #pragma unroll
        for (int it = 0; it < 4; it++) {
            int idx = tid + it * 256;
            int r = idx >> 3, ch = idx & 7;
            *(uint4*)&gsm[r * GSTR + ch * 8] =
                *(const uint4*)&Ah[(size_t)(m0 + r) * K + kc + ch * 8];
            *(uint4*)&gsm[G_AL + r * GSTR + ch * 8] =
                *(const uint4*)&Al[(size_t)(m0 + r) * K + kc + ch * 8];
        }
        #pragma unroll
        for (int it = 0; it < 2; it++) {
            int idx = tid + it * 256;
            int r = idx >> 3, ch = idx & 7;
            *(uint4*)&gsm[G_BH + r * GSTR + ch * 8] =
                *(const uint4*)&Bh[(size_t)(n0 + r) * K + kc + ch * 8];
            *(uint4*)&gsm[G_BL + r * GSTR + ch * 8] =
                *(const uint4*)&Bl[(size_t)(n0 + r) * K + kc + ch * 8];
        }
        __syncthreads();

        uint32_t ah[4][4], al[4][4];
        {
            int octet = lane >> 3;
            int rr = row0 + (octet & 1) * 8 + (lane & 7);
            int kk = (octet >> 1) * 8;
            #pragma unroll
            for (int ks = 0; ks < 4; ks++) {
                LDSM_X4(ah[ks][0], ah[ks][1], ah[ks][2], ah[ks][3],
                        smem_u32(&gsm[rr * GSTR + ks * 16 + kk]));
                LDSM_X4(al[ks][0], al[ks][1], al[ks][2], al[ks][3],
                        smem_u32(&gsm[G_AL + rr * GSTR + ks * 16 + kk]));
            }
        }
        #pragma unroll
        for (int g = 0; g < 2; g++) {
            int rnA = 32 * g + ((lane >> 4) & 1) * 8 + (lane & 7);
            int rnB = rnA + 16;
            int ko = ((lane >> 3) & 1) * 8;
            #pragma unroll
            for (int ks = 0; ks < 4; ks++) {
                uint32_t bhA[4], blA[4], bhB[4], blB[4];
                LDSM_X4(bhA[0], bhA[1], bhA[2], bhA[3],
                        smem_u32(&gsm[G_BH + rnA * GSTR + ks * 16 + ko]));
                LDSM_X4(blA[0], blA[1], blA[2], blA[3],
                        smem_u32(&gsm[G_BL + rnA * GSTR + ks * 16 + ko]));
                LDSM_X4(bhB[0], bhB[1], bhB[2], bhB[3],
                        smem_u32(&gsm[G_BH + rnB * GSTR + ks * 16 + ko]));
                LDSM_X4(blB[0], blB[1], blB[2], blB[3],
                        smem_u32(&gsm[G_BL + rnB * GSTR + ks * 16 + ko]));
                MMA_BF16(at[4 * g + 0], ah[ks], bhA[0], bhA[1]);
                MMA_BF16(at[4 * g + 1], ah[ks], bhA[2], bhA[3]);
                MMA_BF16(at[4 * g + 2], ah[ks], bhB[0], bhB[1]);
                MMA_BF16(at[4 * g + 3], ah[ks], bhB[2], bhB[3]);
                MMA_BF16(at[4 * g + 0], ah[ks], blA[0], blA[1]);
                MMA_BF16(at[4 * g + 1], ah[ks], blA[2], blA[3]);
                MMA_BF16(at[4 * g + 2], ah[ks], blB[0], blB[1]);
                MMA_BF16(at[4 * g + 3], ah[ks], blB[2], blB[3]);
                MMA_BF16(at[4 * g + 0], al[ks], bhA[0], bhA[1]);
                MMA_BF16(at[4 * g + 1], al[ks], bhA[2], bhA[3]);
                MMA_BF16(at[4 * g + 2], al[ks], bhB[0], bhB[1]);
                MMA_BF16(at[4 * g + 3], al[ks], bhB[2], bhB[3]);
            }
        }
    }

    const int gr0 = m0 + row0 + tr, gr1 = gr0 + 8;
    #pragma unroll
    for (int n = 0; n < 8; n++) {
        int col = n0 + n * 8 + tc * 2;
        float b0 = bias ? bias[col] : 0.f;
        float b1 = bias ? bias[col + 1] : 0.f;
        *(float2*)&C[(size_t)gr0 * N + col] = make_float2(at[n][0] + b0, at[n][1] + b1);
        *(float2*)&C[(size_t)gr1 * N + col] = make_float2(at[n][2] + b0, at[n][3] + b1);
    }
}

// ---------------- prep kernels ----------------
__global__ void h_split_kernel(const float* __restrict__ h)
{
    int v = blockIdx.x * blockDim.x + threadIdx.x;
    float4 a = ((const float4*)h)[v];
    __nv_bfloat16 h0 = __float2bfloat16(a.x), h1 = __float2bfloat16(a.y);
    __nv_bfloat16 h2 = __float2bfloat16(a.z), h3 = __float2bfloat16(a.w);
    *(uint2*)&g_hh[4 * v] = make_uint2(pack_bf(h0, h1), pack_bf(h2, h3));
    *(uint2*)&g_hl[4 * v] = make_uint2(
        pack_bf(__float2bfloat16(a.x - __bfloat162float(h0)),
                __float2bfloat16(a.y - __bfloat162float(h1))),
        pack_bf(__float2bfloat16(a.z - __bfloat162float(h2)),
                __float2bfloat16(a.w - __bfloat162float(h3))));
}

struct WEnt { const float* src; int N, row_off, Kd, start, count, dst; float scale; };
struct WAll { WEnt w[9]; int total; };

__global__ void prep_weights_kernel(WAll a)
{
    int idx = blockIdx.x * blockDim.x + threadIdx.x;
    if (idx >= a.total) return;
    #pragma unroll
    for (int e = 0; e < 9; e++) {
        if (idx >= a.w[e].start && idx < a.w[e].start + a.w[e].count) {
            int li = idx - a.w[e].start;
            int k = li / a.w[e].N, n = li % a.w[e].N;
            float v = a.w[e].src[li] * a.w[e].scale;
            __nv_bfloat16 hi = __float2bfloat16(v);
            __nv_bfloat16 lo = __float2bfloat16(v - __bfloat162float(hi));
            size_t o = (size_t)(a.w[e].row_off + n) * a.w[e].Kd + k;
            if (a.w[e].dst == 0)      { g_Wp_h[o] = hi; g_Wp_l[o] = lo; }
            else if (a.w[e].dst == 1) { g_Wi_h[o] = hi; g_Wi_l[o] = lo; }
            else                      { g_Wh_h[o] = hi; g_Wh_l[o] = lo; }
            return;
        }
    }
}

__global__ void bias_cat_kernel(const float* b_msg, const float* b_key, const float* b_qry,
                                const float* bi_r, const float* bi_z, const float* bi_n)
{
    int i = threadIdx.x;
    if (i < 128)      g_bias_p[i] = b_msg[i];
    else if (i < 192) g_bias_p[i] = b_key[i - 128];
    else if (i < 256) g_bias_p[i] = 0.125f * b_qry[i - 192];
    if (i < 256)      g_bias_i[i] = bi_r[i];
    else if (i < 512) g_bias_i[i] = bi_z[i - 256];
    else if (i < 768) g_bias_i[i] = bi_n[i - 512];
}

__global__ void split_qk_kernel()
{
    int i = blockIdx.x * blockDim.x + threadIdx.x;
    int row = i >> 6, c = i & 63;
    float k = g_qkm[(size_t)row * 256 + 128 + c];
    __nv_bfloat16 kh = __float2bfloat16(k);
    g_kh[i] = kh; g_kl[i] = __float2bfloat16(k - __bfloat162float(kh));
    float q = g_qkm[(size_t)row * 256 + 192 + c];
    __nv_bfloat16 qh = __float2bfloat16(q);
    g_qh[i] = qh; g_ql[i] = __float2bfloat16(q - __bfloat162float(qh));
}

__global__ void msgT_split_kernel()
{
    __shared__ float t[32][33];
    int n0 = blockIdx.x * 32, m0 = blockIdx.y * 32;
    #pragma unroll
    for (int i = threadIdx.y; i < 32; i += 8)
        t[i][threadIdx.x] = g_qkm[(size_t)(n0 + i) * 256 + m0 + threadIdx.x];
    __syncthreads();
    #pragma unroll
    for (int i = threadIdx.y; i < 32; i += 8) {
        float v = t[threadIdx.x][i];
        __nv_bfloat16 hi = __float2bfloat16(v);
        size_t o = (size_t)(m0 + i) * N_AGENTS + n0 + threadIdx.x;
        g_mTh[o] = hi;
        g_mTl[o] = __float2bfloat16(v - __bfloat162float(hi));
    }
}

// ---------------- normalization / epilogue kernels ----------------
__global__ void inv_S_kernel()
{
    int i = blockIdx.x * blockDim.x + threadIdx.x;
    g_S[i] = 1.0f / (g_S_part[i] + g_S_part[N_AGENTS + i]);
}

__global__ void norm_attended_kernel()
{
    int v = blockIdx.x * blockDim.x + threadIdx.x;
    float inv = g_S[v >> 5];
    const size_t stride = (size_t)N_AGENTS * MSG / 4;
    float4 a = ((const float4*)g_att_part)[v];
    float4 b = ((const float4*)g_att_part)[v + stride];
    float4 o = make_float4((a.x + b.x) * inv, (a.y + b.y) * inv,
                           (a.z + b.z) * inv, (a.w + b.w) * inv);
    __nv_bfloat16 h0 = __float2bfloat16(o.x), h1 = __float2bfloat16(o.y);
    __nv_bfloat16 h2 = __float2bfloat16(o.z), h3 = __float2bfloat16(o.w);
    *(uint2*)&g_ath[4 * v] = make_uint2(pack_bf(h0, h1), pack_bf(h2, h3));
    *(uint2*)&g_atl[4 * v] = make_uint2(
        pack_bf(__float2bfloat16(o.x - __bfloat162float(h0)),
                __float2bfloat16(o.y - __bfloat162float(h1))),
        pack_bf(__float2bfloat16(o.z - __bfloat162float(h2)),
                __float2bfloat16(o.w - __bfloat162float(h3))));
}

__global__ void norm_attn_kernel(float* __restrict__ E)
{
    int v = blockIdx.x * blockDim.x + threadIdx.x;
    float inv = g_S[v >> 11];
    float4 a = ((const float4*)E)[v];
    a.x *= inv; a.y *= inv; a.z *= inv; a.w *= inv;
    ((float4*)E)[v] = a;
}

__device__ __forceinline__ float sigm(float x) { return 1.f / (1.f + __expf(-x)); }

__global__ void gru_final_kernel(const float* __restrict__ h,
                                 const float* __restrict__ bh_n,
                                 float* __restrict__ out)
{
    int v = blockIdx.x * blockDim.x + threadIdx.x;
    int row = v >> 6, c4 = (v & 63) * 4;
    const float* GA = g_GA + (size_t)row * 768;
    const float* GB = g_GB + (size_t)row * 768;
    float4 gar = *(const float4*)&GA[c4];
    float4 gaz = *(const float4*)&GA[256 + c4];
    float4 gan = *(const float4*)&GA[512 + c4];
    float4 gbr = *(const float4*)&GB[c4];
    float4 gbz = *(const float4*)&GB[256 + c4];
    float4 gbn = *(const float4*)&GB[512 + c4];
    float4 bn  = *(const float4*)&bh_n[c4];
    float4 hh  = ((const float4*)h)[v];
    float4 o;
    { float r = sigm(gar.x + gbr.x), z = sigm(gaz.x + gbz.x);
      float n = tanhf(gan.x + r * (gbn.x + bn.x)); o.x = (1.f - z) * n + z * hh.x; }
    { float r = sigm(gar.y + gbr.y), z = sigm(gaz.y + gbz.y);
      float n = tanhf(gan.y + r * (gbn.y + bn.y)); o.y = (1.f - z) * n + z * hh.y; }
    { float r = sigm(gar.z + gbr.z), z = sigm(gaz.z + gbz.z);
      float n = tanhf(gan.z + r * (gbn.z + bn.z)); o.z = (1.f - z) * n + z * hh.z; }
    { float r = sigm(gar.w + gbr.w), z = sigm(gaz.w + gbz.w);
      float n = tanhf(gan.w + r * (gbn.w + bn.w)); o.w = (1.f - z) * n + z * hh.w; }
    ((float4*)out)[v] = o;
}

// ---------------- launch ----------------
extern "C" void kernel_launch(void* const* d_in, const int* in_sizes, int n_in,
                              void* d_out, int out_size)
{
    const float* h     = (const float*)d_in[0];
    const float* W_msg = (const float*)d_in[1];
    const float* b_msg = (const float*)d_in[2];
    const float* W_key = (const float*)d_in[3];
    const float* b_key = (const float*)d_in[4];
    const float* W_qry = (const float*)d_in[5];
    const float* b_qry = (const float*)d_in[6];
    const float* Wi_r  = (const float*)d_in[7];
    const float* bi_r  = (const float*)d_in[8];
    const float* Wi_z  = (const float*)d_in[9];
    const float* bi_z  = (const float*)d_in[10];
    const float* Wi_n  = (const float*)d_in[11];
    const float* bi_n  = (const float*)d_in[12];
    const float* Wh_r  = (const float*)d_in[13];
    const float* Wh_z  = (const float*)d_in[14];
    const float* Wh_n  = (const float*)d_in[15];
    const float* bh_n  = (const float*)d_in[16];

    float* out    = (float*)d_out;
    float* h_new  = out;
    float* attn   = out + (size_t)N_AGENTS * HIDDEN;

    float *p_qkm, *p_GA, *p_GB, *p_bias_p, *p_bias_i;
    __nv_bfloat16 *p_hh, *p_hl, *p_ath, *p_atl;
    __nv_bfloat16 *p_Wp_h, *p_Wp_l, *p_Wi_h, *p_Wi_l, *p_Wh_h, *p_Wh_l;
    cudaGetSymbolAddress((void**)&p_qkm, g_qkm);
    cudaGetSymbolAddress((void**)&p_GA, g_GA);
    cudaGetSymbolAddress((void**)&p_GB, g_GB);
    cudaGetSymbolAddress((void**)&p_bias_p, g_bias_p);
    cudaGetSymbolAddress((void**)&p_bias_i, g_bias_i);
    cudaGetSymbolAddress((void**)&p_hh, g_hh);
    cudaGetSymbolAddress((void**)&p_hl, g_hl);
    cudaGetSymbolAddress((void**)&p_ath, g_ath);
    cudaGetSymbolAddress((void**)&p_atl, g_atl);
    cudaGetSymbolAddress((void**)&p_Wp_h, g_Wp_h);
    cudaGetSymbolAddress((void**)&p_Wp_l, g_Wp_l);
    cudaGetSymbolAddress((void**)&p_Wi_h, g_Wi_h);
    cudaGetSymbolAddress((void**)&p_Wi_l, g_Wi_l);
    cudaGetSymbolAddress((void**)&p_Wh_h, g_Wh_h);
    cudaGetSymbolAddress((void**)&p_Wh_l, g_Wh_l);

    cudaFuncSetAttribute(attn_mma_kernel, cudaFuncAttributeMaxDynamicSharedMemorySize, ATTN_SMEM);
    cudaFuncSetAttribute(gemm_tc, cudaFuncAttributeMaxDynamicSharedMemorySize, GEMM_SMEM);

    WAll wa;
    int off = 0;
    auto add = [&](int e, const float* src, int K, int N, int row_off, int Kd, int dst, float sc) {
        wa.w[e] = WEnt{src, N, row_off, Kd, off, K * N, dst, sc};
        off += K * N;
    };
    add(0, W_msg, 256, 128, 0,   256, 0, 1.0f);
    add(1, W_key, 256, 64,  128, 256, 0, 1.0f);
    add(2, W_qry, 256, 64,  192, 256, 0, 0.125f);
    add(3, Wi_r,  128, 256, 0,   128, 1, 1.0f);
    add(4, Wi_z,  128, 256, 256, 128, 1, 1.0f);
    add(5, Wi_n,  128, 256, 512, 128, 1, 1.0f);
    add(6, Wh_r,  256, 256, 0,   256, 2, 1.0f);
    add(7, Wh_z,  256, 256, 256, 256, 2, 1.0f);
    add(8, Wh_n,  256, 256, 512, 256, 2, 1.0f);
    wa.total = off;

    h_split_kernel<<<(N_AGENTS * HIDDEN / 4) / 256, 256>>>(h);
    bias_cat_kernel<<<1, 1024>>>(b_msg, b_key, b_qry, bi_r, bi_z, bi_n);
    prep_weights_kernel<<<(wa.total + 255) / 256, 256>>>(wa);

    // fused projection: qkm = h @ [W_msg | W_key | 0.125*W_qry] + bias
    gemm_tc<<<dim3(4, N_AGENTS / 128), 256, GEMM_SMEM>>>(
        p_hh, p_hl, p_Wp_h, p_Wp_l, p_bias_p, p_qkm, 256, 256);
    split_qk_kernel<<<(N_AGENTS * KEY) / 256, 256>>>();
    msgT_split_kernel<<<dim3(N_AGENTS / 32, MSG / 32), dim3(32, 8)>>>();

    // fused tensor-core attention (R8 config: double-buffered, 1 block/SM)
    attn_mma_kernel<<<dim3(N_AGENTS / 128, NSPLIT), 256, ATTN_SMEM>>>(attn);

    inv_S_kernel<<<N_AGENTS / 256, 256>>>();
    norm_attended_kernel<<<(N_AGENTS * MSG / 4) / 256, 256>>>();
    norm_attn_kernel<<<(int)(((size_t)N_AGENTS * N_AGENTS / 4) / 256), 256>>>(attn);

    // GRU gates
    gemm_tc<<<dim3(12, N_AGENTS / 128), 256, GEMM_SMEM>>>(
        p_ath, p_atl, p_Wi_h, p_Wi_l, p_bias_i, p_GA, 128, 768);
    gemm_tc<<<dim3(12, N_AGENTS / 128), 256, GEMM_SMEM>>>(
        p_hh, p_hl, p_Wh_h, p_Wh_l, nullptr, p_GB, 256, 768);

    gru_final_kernel<<<(N_AGENTS * HIDDEN / 4) / 256, 256>>>(h, bh_n, h_new);
}